// round 1
// baseline (speedup 1.0000x reference)
#include <cuda_runtime.h>
#include <cuda_bf16.h>

// Problem constants (fixed by the reference)
#define N_NODES 8192
#define K_NB    64
#define F_DIM   128
#define ROW_LEN (2 * F_DIM + 1)            // 257
#define TOTAL_E (N_NODES * K_NB)           // 524288 write events
#define SAMPLES_ELEMS ((long long)TOTAL_E * ROW_LEN)
#define TILE_R  128                        // rows per fill tile
#define SORT_CAP 512                       // bucket sort capacity (binomial mean 64, sd 8)

// Scratch (allocation-free: __device__ globals)
__device__ int g_count[N_NODES];
__device__ int g_off[N_NODES + 1];
__device__ int g_cursor[N_NODES];
__device__ int g_ts[TOTAL_E];              // timestamps bucketed by column

// ---------------------------------------------------------------------------
// samples: out[(i*K+j)*257 + pos] = { emb[i][pos]            pos < 128
//                                     emb[idx][pos-128]      128 <= pos < 256
//                                     sum_weights[idx]       pos == 256 }
// One block per node i; node row cached in smem; fully coalesced stores.
// ---------------------------------------------------------------------------
__global__ void samples_kernel(const float* __restrict__ emb,
                               const float* __restrict__ sw,
                               const int*   __restrict__ idx_in,
                               float* __restrict__ out) {
    __shared__ float node[F_DIM];
    const int i = blockIdx.x;
    const int t = threadIdx.x;               // 256 threads
    if (t < F_DIM) node[t] = __ldg(&emb[(long long)i * F_DIM + t]);
    __syncthreads();

    for (int j = 0; j < K_NB; j++) {
        const int c = (j < K_NB - 1) ? __ldg(&idx_in[i * (K_NB - 1) + j]) : i;
        const long long base = (long long)(i * K_NB + j) * ROW_LEN;
        float v;
        if (t < F_DIM) v = node[t];
        else           v = __ldg(&emb[(long long)c * F_DIM + (t - F_DIM)]);
        out[base + t] = v;
        if (t == 0) out[base + 2 * F_DIM] = __ldg(&sw[c]);
    }
}

// ---------------------------------------------------------------------------
// adj pipeline
// ---------------------------------------------------------------------------
__global__ void zero_kernel() {
    int i = blockIdx.x * blockDim.x + threadIdx.x;
    if (i < N_NODES) g_count[i] = 0;
}

__device__ __forceinline__ int event_col(const int* __restrict__ idx_in, int e) {
    int r = e >> 6;          // e / K
    int j = e & (K_NB - 1);  // e % K
    return (j < K_NB - 1) ? __ldg(&idx_in[r * (K_NB - 1) + j]) : r;
}

__global__ void hist_kernel(const int* __restrict__ idx_in) {
    int e = blockIdx.x * blockDim.x + threadIdx.x;
    if (e >= TOTAL_E) return;
    atomicAdd(&g_count[event_col(idx_in, e)], 1);
}

// Exclusive prefix scan of 8192 counts with one 1024-thread block.
__global__ void scan_kernel() {
    __shared__ int part[1024];
    const int t = threadIdx.x;
    int local[8];
    int s = 0;
    #pragma unroll
    for (int k = 0; k < 8; k++) { local[k] = s; s += g_count[t * 8 + k]; }
    part[t] = s;
    __syncthreads();
    for (int d = 1; d < 1024; d <<= 1) {
        int v = (t >= d) ? part[t - d] : 0;
        __syncthreads();
        if (t >= d) part[t] += v;
        __syncthreads();
    }
    const int base = (t == 0) ? 0 : part[t - 1];
    #pragma unroll
    for (int k = 0; k < 8; k++) {
        int o = base + local[k];
        g_off[t * 8 + k]    = o;
        g_cursor[t * 8 + k] = o;
    }
    if (t == 1023) g_off[N_NODES] = part[1023];
}

__global__ void scatter_kernel(const int* __restrict__ idx_in) {
    int e = blockIdx.x * blockDim.x + threadIdx.x;
    if (e >= TOTAL_E) return;
    int c = event_col(idx_in, e);
    int p = atomicAdd(&g_cursor[c], 1);
    g_ts[p] = e;                     // value recoverable as edge_out[e]
}

// Sort each column's bucket by timestamp (bitonic in smem). Atomic scatter
// order is nondeterministic; the sort makes the result deterministic.
__global__ void sort_kernel() {
    __shared__ int s[SORT_CAP];
    const int c   = blockIdx.x;
    const int beg = g_off[c], end = g_off[c + 1];
    const int m   = end - beg;
    if (m <= 1) return;
    if (m <= SORT_CAP) {
        for (int i = threadIdx.x; i < SORT_CAP; i += blockDim.x)
            s[i] = (i < m) ? g_ts[beg + i] : 0x7fffffff;
        __syncthreads();
        for (int k = 2; k <= SORT_CAP; k <<= 1) {
            for (int j = k >> 1; j > 0; j >>= 1) {
                for (int i = threadIdx.x; i < SORT_CAP; i += blockDim.x) {
                    int ixj = i ^ j;
                    if (ixj > i) {
                        bool up = ((i & k) == 0);
                        int a = s[i], b = s[ixj];
                        if ((a > b) == up) { s[i] = b; s[ixj] = a; }
                    }
                }
                __syncthreads();
            }
        }
        for (int i = threadIdx.x; i < m; i += blockDim.x) g_ts[beg + i] = s[i];
    } else if (threadIdx.x == 0) {
        // statistically unreachable fallback (m ~ Binom(524288, 1/8192))
        for (int i = beg + 1; i < end; i++) {
            int v = g_ts[i], j = i - 1;
            while (j >= beg && g_ts[j] > v) { g_ts[j + 1] = g_ts[j]; j--; }
            g_ts[j + 1] = v;
        }
    }
}

// Forward-fill: thread owns column c, tile of TILE_R rows. Binary search the
// carry-in at the tile boundary, then stream coalesced row-major stores.
__global__ void fill_kernel(const float* __restrict__ edge_out,
                            float* __restrict__ adj) {
    const int c  = blockIdx.x * blockDim.x + threadIdx.x;
    const int r0 = blockIdx.y * TILE_R;
    const int beg = g_off[c], end = g_off[c + 1];

    // first bucket entry with row >= r0  (ts = r*K + j, so row>=r0 <=> ts>=r0*K)
    int lo = beg, hi = end;
    const int bound = r0 * K_NB;
    while (lo < hi) {
        int mid = (lo + hi) >> 1;
        if (g_ts[mid] < bound) lo = mid + 1; else hi = mid;
    }
    int p = lo;
    float val = (p > beg) ? __ldg(&edge_out[g_ts[p - 1]]) : 0.0f;

    long long out_off = (long long)r0 * N_NODES + c;
    #pragma unroll 4
    for (int i = 0; i < TILE_R; i++) {
        const int lim = (r0 + i + 1) * K_NB;   // all events with row <= r0+i
        while (p < end && g_ts[p] < lim) { val = __ldg(&edge_out[g_ts[p]]); p++; }
        adj[out_off] = val;
        out_off += N_NODES;
    }
}

// ---------------------------------------------------------------------------
extern "C" void kernel_launch(void* const* d_in, const int* in_sizes, int n_in,
                              void* d_out, int out_size) {
    const float* emb      = (const float*)d_in[0];   // [8192, 128]
    const float* sw       = (const float*)d_in[1];   // [8192]
    const int*   idx_in   = (const int*)  d_in[2];   // [8192, 63]
    const float* edge_out = (const float*)d_in[3];   // [8192, 64]
    float* out = (float*)d_out;
    float* adj = out + SAMPLES_ELEMS;                // adj follows samples

    samples_kernel<<<N_NODES, 256>>>(emb, sw, idx_in, out);

    zero_kernel   <<<N_NODES / 256, 256>>>();
    hist_kernel   <<<TOTAL_E / 256, 256>>>(idx_in);
    scan_kernel   <<<1, 1024>>>();
    scatter_kernel<<<TOTAL_E / 256, 256>>>(idx_in);
    sort_kernel   <<<N_NODES, 128>>>();
    fill_kernel   <<<dim3(N_NODES / 256, N_NODES / TILE_R), 256>>>(edge_out, adj);
}

// round 2
// speedup vs baseline: 1.1601x; 1.1601x over previous
#include <cuda_runtime.h>
#include <cuda_bf16.h>

// Problem constants (fixed by the reference)
#define N_NODES 8192
#define K_NB    64
#define F_DIM   128
#define ROW_LEN 257                         // 2F+1
#define TOTAL_E (N_NODES * K_NB)            // 524288 write events
#define SAMPLES_ELEMS ((long long)TOTAL_E * ROW_LEN)
#define TILE_R  128                         // rows per fill tile
#define BKT     256                         // fixed bucket capacity per column
#define FILL_BLKS 512                       // 64 row-tiles * 8 col-blocks

// Scratch (allocation-free __device__ globals)
__device__ int g_cnt[N_NODES];
__device__ int g_bkt[N_NODES * BKT];        // 8 MB: timestamps bucketed by column

// ---------------------------------------------------------------------------
__global__ void zero_kernel() {
    g_cnt[blockIdx.x * blockDim.x + threadIdx.x] = 0;
}

// Scatter each write-event's timestamp into its column bucket.
// ts = r*K + j fully determines the value (edge_out[ts]) and the ordering.
__global__ void scatter_kernel(const int* __restrict__ idx_in) {
    const int e = blockIdx.x * blockDim.x + threadIdx.x;
    const int r = e >> 6;
    const int j = e & (K_NB - 1);
    const int c = (j < K_NB - 1) ? __ldg(&idx_in[r * (K_NB - 1) + j]) : r;
    const int p = atomicAdd(&g_cnt[c], 1);
    if (p < BKT) g_bkt[c * BKT + p] = e;    // capacity 256 vs mean 64: never clips
}

// Sort each column bucket ascending by timestamp (bitonic, 256-wide pad).
// Makes the atomic-scatter order deterministic.
__global__ void sort_kernel() {
    __shared__ int s[BKT];
    const int c = blockIdx.x;
    int m = g_cnt[c]; if (m > BKT) m = BKT;
    if (m <= 1) return;
    int* __restrict__ b = &g_bkt[c * BKT];
    for (int i = threadIdx.x; i < BKT; i += 128) s[i] = (i < m) ? b[i] : 0x7fffffff;
    __syncthreads();
    for (int k = 2; k <= BKT; k <<= 1) {
        for (int j = k >> 1; j > 0; j >>= 1) {
            for (int i = threadIdx.x; i < BKT; i += 128) {
                const int ixj = i ^ j;
                if (ixj > i) {
                    const bool up = ((i & k) == 0);
                    const int a = s[i], bb = s[ixj];
                    if ((a > bb) == up) { s[i] = bb; s[ixj] = a; }
                }
            }
            __syncthreads();
        }
    }
    for (int i = threadIdx.x; i < m; i += 128) b[i] = s[i];
}

// ---------------------------------------------------------------------------
// Fused output kernel: fill (adj forward-fill) + samples (gather-concat),
// both with float4 stores, running concurrently on one grid.
// ---------------------------------------------------------------------------
__global__ void __launch_bounds__(256) fused_kernel(
    const float* __restrict__ emb,
    const float* __restrict__ sw,
    const int*   __restrict__ idx_in,
    const float* __restrict__ edge,
    float* __restrict__ out)
{
    if (blockIdx.x < FILL_BLKS) {
        // ---------------- adj forward-fill: 4 columns per thread ----------
        float* __restrict__ adj = out + SAMPLES_ELEMS;
        const int b    = blockIdx.x;
        const int r0   = (b >> 3) * TILE_R;
        const int c0   = (b & 7) * 1024 + threadIdx.x * 4;

        int   p[4], mend[4];
        float val[4];
        #pragma unroll
        for (int u = 0; u < 4; u++) {
            const int c = c0 + u;
            const int* __restrict__ bb = &g_bkt[c * BKT];
            int m = g_cnt[c]; if (m > BKT) m = BKT;
            int lo = 0, hi = m;
            const int bound = r0 * K_NB;          // first event with row >= r0
            while (lo < hi) {
                const int mid = (lo + hi) >> 1;
                if (__ldg(&bb[mid]) < bound) lo = mid + 1; else hi = mid;
            }
            p[u] = lo; mend[u] = m;
            val[u] = (lo > 0) ? __ldg(&edge[__ldg(&bb[lo - 1])]) : 0.0f;
        }

        long long off = (long long)r0 * N_NODES + c0;
        for (int i = 0; i < TILE_R; i++) {
            const int lim = (r0 + i + 1) * K_NB;  // events with row <= r0+i
            float4 v;
            #pragma unroll
            for (int u = 0; u < 4; u++) {
                const int* __restrict__ bb = &g_bkt[(c0 + u) * BKT];
                while (p[u] < mend[u] && __ldg(&bb[p[u]]) < lim) {
                    val[u] = __ldg(&edge[__ldg(&bb[p[u]])]);
                    p[u]++;
                }
                ((float*)&v)[u] = val[u];
            }
            *(float4*)(adj + off) = v;
            off += N_NODES;
        }
    } else {
        // ---------------- samples: one node per block, float4 stores ------
        const int i = blockIdx.x - FILL_BLKS;
        const int t = threadIdx.x;

        __shared__ float node_row[F_DIM];
        __shared__ int   nidx[K_NB];
        if (t < F_DIM) node_row[t] = __ldg(&emb[(long long)i * F_DIM + t]);
        if (t < K_NB)  nidx[t] = (t < K_NB - 1) ? __ldg(&idx_in[i * (K_NB - 1) + t]) : i;
        __syncthreads();

        // 4 sample-rows = 1028 floats = 257 aligned float4s per group; 16 groups.
        float4* __restrict__ outv = (float4*)(out + (long long)i * K_NB * ROW_LEN);
        for (int g = 0; g < 16; g++) {
            const int j0 = g * 4;
            for (int q = t; q < 257; q += 256) {
                const int f = 4 * q;
                float4 v;
                #pragma unroll
                for (int lane = 0; lane < 4; lane++) {
                    const int ff  = f + lane;
                    const int row = (ff >= 257) + (ff >= 514) + (ff >= 771);
                    const int col = ff - row * ROW_LEN;
                    const int c   = nidx[j0 + row];
                    float x;
                    if (col < F_DIM)          x = node_row[col];
                    else if (col < 2 * F_DIM) x = __ldg(&emb[(long long)c * F_DIM + (col - F_DIM)]);
                    else                      x = __ldg(&sw[c]);
                    ((float*)&v)[lane] = x;
                }
                outv[g * 257 + q] = v;
            }
        }
    }
}

// ---------------------------------------------------------------------------
extern "C" void kernel_launch(void* const* d_in, const int* in_sizes, int n_in,
                              void* d_out, int out_size) {
    const float* emb      = (const float*)d_in[0];   // [8192, 128]
    const float* sw       = (const float*)d_in[1];   // [8192]
    const int*   idx_in   = (const int*)  d_in[2];   // [8192, 63]
    const float* edge_out = (const float*)d_in[3];   // [8192, 64]
    float* out = (float*)d_out;

    zero_kernel   <<<N_NODES / 1024, 1024>>>();
    scatter_kernel<<<TOTAL_E / 256, 256>>>(idx_in);
    sort_kernel   <<<N_NODES, 128>>>();
    fused_kernel  <<<FILL_BLKS + N_NODES, 256>>>(emb, sw, idx_in, edge_out, out);
}

// round 3
// speedup vs baseline: 1.9809x; 1.7076x over previous
#include <cuda_runtime.h>
#include <cuda_bf16.h>

// Problem constants (fixed by the reference)
#define N_NODES 8192
#define K_NB    64
#define F_DIM   128
#define ROW_LEN 257                         // 2F+1
#define TOTAL_E (N_NODES * K_NB)            // 524288 write events
#define SAMPLES_ELEMS ((long long)TOTAL_E * ROW_LEN)
#define TILE_R   128                        // rows per fill tile
#define N_TILES  (N_NODES / TILE_R)         // 64
#define CAP      16                         // per-(col,tile) bucket cap (Poisson(1))
#define NB       (N_NODES * N_TILES)        // 524288 micro-buckets
#define FILL_BLKS 512                       // 64 row-tiles * 8 col-blocks

// Scratch (allocation-free __device__ globals)
__device__ int g_cnt[NB];                   // 2 MB  events per (col,tile)
__device__ int g_bkt[NB * CAP];             // 32 MB timestamps
__device__ int g_bmax[NB];                  // 2 MB  max ts in bucket (-1 if empty)
__device__ int g_carry[NB];                 // 2 MB  max ts in tiles < t (-1 if none)

// ---------------------------------------------------------------------------
__global__ void zero_kernel() {
    g_cnt[blockIdx.x * blockDim.x + threadIdx.x] = 0;
}

// Scatter each event ts = r*K+j into micro-bucket (col, r/TILE_R).
__global__ void scatter_kernel(const int* __restrict__ idx_in) {
    const int e = blockIdx.x * blockDim.x + threadIdx.x;
    const int r = e >> 6;
    const int j = e & (K_NB - 1);
    const int c = (j < K_NB - 1) ? __ldg(&idx_in[r * (K_NB - 1) + j]) : r;
    const int bid = c * N_TILES + (r >> 7);
    const int p = atomicAdd(&g_cnt[bid], 1);
    if (p < CAP) g_bkt[bid * CAP + p] = e;
}

// Sort each micro-bucket (mean 1 event) and record its max ts.
__global__ void sortbkt_kernel() {
    const int b = blockIdx.x * blockDim.x + threadIdx.x;
    int m = g_cnt[b]; if (m > CAP) m = CAP;
    int* __restrict__ a = &g_bkt[b * CAP];
    for (int i = 1; i < m; i++) {
        int v = a[i], j = i - 1;
        while (j >= 0 && a[j] > v) { a[j + 1] = a[j]; j--; }
        a[j + 1] = v;
    }
    g_bmax[b] = (m > 0) ? a[m - 1] : -1;
}

// Warp per column: exclusive prefix-max of bmax over the 64 tiles -> carry ts.
__global__ void carry_kernel() {
    const int c    = blockIdx.x * (blockDim.x / 32) + (threadIdx.x >> 5);
    const int lane = threadIdx.x & 31;
    const int base = c * N_TILES;
    const int v0 = g_bmax[base + 2 * lane];
    const int v1 = g_bmax[base + 2 * lane + 1];
    int x = max(v0, v1);
    #pragma unroll
    for (int d = 1; d < 32; d <<= 1) {
        int y = __shfl_up_sync(0xffffffffu, x, d);
        if (lane >= d) x = max(x, y);
    }
    int P = __shfl_up_sync(0xffffffffu, x, 1);
    if (lane == 0) P = -1;
    g_carry[base + 2 * lane]     = P;
    g_carry[base + 2 * lane + 1] = max(P, v0);
}

// ---------------------------------------------------------------------------
// Fused output kernel: adj forward-fill + samples gather-concat, float4 stores.
// ---------------------------------------------------------------------------
__global__ void __launch_bounds__(256) fused_kernel(
    const float* __restrict__ emb,
    const float* __restrict__ sw,
    const int*   __restrict__ idx_in,
    const float* __restrict__ edge,
    float* __restrict__ out)
{
    if (blockIdx.x < FILL_BLKS) {
        // ---- adj fill: thread owns 4 adjacent columns within one row tile --
        float* __restrict__ adj = out + SAMPLES_ELEMS;
        const int b  = blockIdx.x;
        const int tt = b >> 3;                       // tile index
        const int r0 = tt * TILE_R;
        const int c0 = (b & 7) * 1024 + threadIdx.x * 4;

        int   pos[4], m[4], nxt[4], base[4];
        float val[4];
        #pragma unroll
        for (int u = 0; u < 4; u++) {
            const int bid = (c0 + u) * N_TILES + tt;
            int mm = __ldg(&g_cnt[bid]); if (mm > CAP) mm = CAP;
            m[u] = mm; base[u] = bid * CAP; pos[u] = 0;
            nxt[u] = (mm > 0) ? __ldg(&g_bkt[bid * CAP]) : 0x7fffffff;
            const int cts = __ldg(&g_carry[bid]);
            val[u] = (cts >= 0) ? __ldg(&edge[cts]) : 0.0f;
        }

        long long off = (long long)r0 * N_NODES + c0;
        for (int i = 0; i < TILE_R; i++) {
            const int lim = (r0 + i + 1) * K_NB;     // events with row <= r0+i
            float4 v;
            #pragma unroll
            for (int u = 0; u < 4; u++) {
                while (nxt[u] < lim) {               // register compare; rare advance
                    val[u] = __ldg(&edge[nxt[u]]);
                    pos[u]++;
                    nxt[u] = (pos[u] < m[u]) ? __ldg(&g_bkt[base[u] + pos[u]])
                                             : 0x7fffffff;
                }
                ((float*)&v)[u] = val[u];
            }
            *(float4*)(adj + off) = v;
            off += N_NODES;
        }
    } else {
        // ---- samples: one node per block; per-lane mapping hoisted ---------
        const int i = blockIdx.x - FILL_BLKS;
        const int t = threadIdx.x;

        __shared__ float node_row[F_DIM];
        __shared__ int4  nidx4[16];                  // 64 neighbor indices
        if (t < F_DIM) node_row[t] = __ldg(&emb[i * F_DIM + t]);
        if (t < K_NB)  ((int*)nidx4)[t] =
            (t < K_NB - 1) ? __ldg(&idx_in[i * (K_NB - 1) + t]) : i;
        __syncthreads();

        float4* __restrict__ outv = (float4*)(out + (long long)i * K_NB * ROW_LEN);

        // Thread t covers q = t; thread 0 also covers q = 256.
        const int nq = (t == 0) ? 2 : 1;
        for (int s = 0; s < nq; s++) {
            const int q = (s == 0) ? t : 256;
            // Fixed per-lane classification (identical across all 16 groups).
            int   row_l[4], col_l[4];
            float nodev[4];
            #pragma unroll
            for (int l = 0; l < 4; l++) {
                const int ff = 4 * q + l;
                const int rw = (ff >= 257) + (ff >= 514) + (ff >= 771);
                row_l[l] = rw;
                col_l[l] = ff - rw * ROW_LEN;
                nodev[l] = (col_l[l] < F_DIM) ? node_row[col_l[l]] : 0.0f;
            }
            #pragma unroll 4
            for (int g = 0; g < 16; g++) {
                const int4 nb = nidx4[g];            // neighbor ids for rows 4g..4g+3
                float4 v;
                #pragma unroll
                for (int l = 0; l < 4; l++) {
                    const int rw = row_l[l];
                    const int c  = (rw == 0) ? nb.x : (rw == 1) ? nb.y
                                 : (rw == 2) ? nb.z : nb.w;
                    const int col = col_l[l];
                    float x;
                    if (col < F_DIM)          x = nodev[l];
                    else if (col < 2 * F_DIM) x = __ldg(&emb[c * F_DIM + (col - F_DIM)]);
                    else                      x = __ldg(&sw[c]);
                    ((float*)&v)[l] = x;
                }
                outv[g * 257 + q] = v;
            }
        }
    }
}

// ---------------------------------------------------------------------------
extern "C" void kernel_launch(void* const* d_in, const int* in_sizes, int n_in,
                              void* d_out, int out_size) {
    const float* emb      = (const float*)d_in[0];   // [8192, 128]
    const float* sw       = (const float*)d_in[1];   // [8192]
    const int*   idx_in   = (const int*)  d_in[2];   // [8192, 63]
    const float* edge_out = (const float*)d_in[3];   // [8192, 64]
    float* out = (float*)d_out;

    zero_kernel   <<<NB / 1024, 1024>>>();
    scatter_kernel<<<TOTAL_E / 256, 256>>>(idx_in);
    sortbkt_kernel<<<NB / 256, 256>>>();
    carry_kernel  <<<N_NODES / 8, 256>>>();          // 8 warps/block, warp per column
    fused_kernel  <<<FILL_BLKS + N_NODES, 256>>>(emb, sw, idx_in, edge_out, out);
}